// round 17
// baseline (speedup 1.0000x reference)
#include <cuda_runtime.h>
#include <stdint.h>

// BasedKernel feature map, d=16:
//   out[row, 0]        = 1
//   out[row, 1..16]    = x[row, j-1] * 0.5
//   out[row, 17+idx]   = x[row, idx>>4] * x[row, idx&15] * SC2,  idx = 0..255
//
// R17 = R15 (best: 43.1us bench) + L2::evict_first on input loads, using
// the ptxas-legal scalar form: createpolicy + ld.global.nc.L2::cache_hint
// (R16's bare .L2::evict_first modifier is vector-only on sm_103).
// R15's finding: evict_first on the write-once output cut wallclock 13%
// via inter-replay L2 hygiene. Input x is read-once (16MB/replay); same
// policy keeps its dead lines out of L2.
//
// Proven structure: 4 rows / 128 threads, one warp per row, x one-value-
// per-lane (no local-memory spill), hoisted-shfl quadratic decomposition
// (idx = 32m+lane -> i = 2m+(lane>>4), k = lane&15), smem staging, single
// 1-D cp.async.bulk flush per block with evict_first policy.

#define SC2 0.17677669529663687f

#define ROWS_PER_BLOCK 4
#define THREADS        128
#define FLOATS_PER_BLOCK (ROWS_PER_BLOCK * 273)      // 1092
#define BYTES_PER_BLOCK  (FLOATS_PER_BLOCK * 4)      // 4368, multiple of 16

__global__ void __launch_bounds__(THREADS, 16)
based_feature_kernel(const float* __restrict__ x,
                     float* __restrict__ out)
{
    __shared__ __align__(16) float buf[FLOATS_PER_BLOCK];

    const int tid  = threadIdx.x;
    const int warp = tid >> 5;                 // 0..3 = local row
    const int lane = tid & 31;
    const int row  = blockIdx.x * ROWS_PER_BLOCK + warp;

    // ---- Phase 1: one row per warp, x resident one-value-per-lane ----
    // Read-once input: non-coherent load with evict_first cache policy
    // (scalar loads need the .L2::cache_hint + createpolicy form).
    const float* xr = x + (size_t)row * 16;
    float v = 0.0f;
    if (lane < 16) {
        asm volatile(
            "{\n\t"
            ".reg .b64 pol;\n\t"
            "createpolicy.fractional.L2::evict_first.b64 pol, 1.0;\n\t"
            "ld.global.nc.L2::cache_hint.f32 %0, [%1], pol;\n\t"
            "}"
            : "=f"(v) : "l"(xr + lane));
    }

    float* o = buf + warp * 273;

    // Convergent shfls (full warp participates; never inside divergence).
    const float b2 = __shfl_sync(0xffffffffu, v, lane & 15) * SC2;  // k-operand
    const int   hi = lane >> 4;                                     // 0 or 1

    // Header (shfl-free, predicated stores only).
    if (lane < 16) o[1 + lane] = v * 0.5f;
    if (lane == 16) o[0] = 1.0f;

    // Quadratic part: idx = 32m + lane, i = 2m + hi, k = lane&15.
#pragma unroll
    for (int m = 0; m < 8; ++m) {
        const float a = __shfl_sync(0xffffffffu, v, 2 * m + hi);
        o[17 + 32 * m + lane] = a * b2;
    }

    __syncthreads();

    // ---- Phase 2: single 1-D TMA bulk store smem -> gmem (bypasses L1),
    //      with L2::evict_first policy on the write-once output stream ----
    if (tid == 0) {
        uint32_t saddr;
        asm volatile(
            "{ .reg .u64 t; cvta.to.shared.u64 t, %1; cvt.u32.u64 %0, t; }"
            : "=r"(saddr) : "l"(buf));

        float* g = out + (size_t)blockIdx.x * FLOATS_PER_BLOCK;
        const int nbytes = BYTES_PER_BLOCK;

        // Order generic-proxy smem writes before the async-proxy read.
        asm volatile("fence.proxy.async.shared::cta;" ::: "memory");
        asm volatile(
            "{\n\t"
            ".reg .b64 pol;\n\t"
            "createpolicy.fractional.L2::evict_first.b64 pol, 1.0;\n\t"
            "cp.async.bulk.global.shared::cta.bulk_group.L2::cache_hint "
            "[%0], [%1], %2, pol;\n\t"
            "}"
            :: "l"(g), "r"(saddr), "r"(nbytes) : "memory");
        asm volatile("cp.async.bulk.commit_group;" ::: "memory");
        // Keep the CTA (and its smem) alive until the bulk read completes.
        asm volatile("cp.async.bulk.wait_group.read 0;" ::: "memory");
    }
}

extern "C" void kernel_launch(void* const* d_in, const int* in_sizes, int n_in,
                              void* d_out, int out_size)
{
    const float* x = (const float*)d_in[0];
    float* out = (float*)d_out;

    const int n_rows = in_sizes[0] / 16;              // 262144
    const int blocks = n_rows / ROWS_PER_BLOCK;       // 65536 (exact)

    based_feature_kernel<<<blocks, THREADS>>>(x, out);
}